// round 4
// baseline (speedup 1.0000x reference)
#include <cuda_runtime.h>
#include <cuda_bf16.h>
#include <cstdint>

#define NUM_NODES 20000
#define SEQ_LEN 128
#define HIDDEN 32
#define N_TOTAL (NUM_NODES * SEQ_LEN)        // 2,560,000
#define N_EDGES 2000000

// Scratch: pre-transform aggregate (2 floats per position) + degree. 20MB + 10MB.
__device__ float g_agg2[(size_t)N_TOTAL * 2];
__device__ float g_deg[N_TOTAL];

// ---------------------------------------------------------------------------
// GCN kernels (edge_index arrives as int32)
// ---------------------------------------------------------------------------

__global__ void deg_kernel(const int* __restrict__ ei, float* __restrict__ deg) {
    int e = blockIdx.x * blockDim.x + threadIdx.x;
    if (e < N_EDGES) {
        int dst = ei[N_EDGES + e];
        atomicAdd(deg + dst, 1.0f);
    }
}

__global__ void dinv_kernel(float* __restrict__ deg) {
    int i = blockIdx.x * blockDim.x + threadIdx.x;
    if (i < N_TOTAL) {
        deg[i] = rsqrtf(deg[i] + 1.0f);
    }
}

// thread per edge: agg2[dst] += x[src] * norm   (GCN linearity: W applied later)
__global__ void edge_scatter2(const int* __restrict__ ei,
                              const float* __restrict__ x,
                              const float* __restrict__ dinv,
                              float* __restrict__ agg2) {
    int e = blockIdx.x * blockDim.x + threadIdx.x;
    if (e >= N_EDGES) return;
    int src = ei[e];
    int dst = ei[N_EDGES + e];
    float norm = dinv[src] * dinv[dst];
    float2 xv = *(const float2*)(x + 2 * (size_t)src);
    float* p = agg2 + 2 * (size_t)dst;
    atomicAdd(p, xv.x * norm);
    atomicAdd(p + 1, xv.y * norm);
}

// ---------------------------------------------------------------------------
// LSTM: 2 threads per node (u-halves), packed f32x2 FMA, shuffle h-exchange.
// ---------------------------------------------------------------------------

typedef unsigned long long ull;

__device__ __forceinline__ ull ffma2(ull a, ull b, ull c) {
    ull d;
    asm("fma.rn.f32x2 %0, %1, %2, %3;" : "=l"(d) : "l"(a), "l"(b), "l"(c));
    return d;
}
__device__ __forceinline__ ull pk(float lo, float hi) {
    ull r;
    asm("mov.b64 %0, {%1, %2};" : "=l"(r) : "f"(lo), "f"(hi));
    return r;
}
__device__ __forceinline__ float2 upk(ull v) {
    float2 r;
    asm("mov.b64 {%0, %1}, %2;" : "=f"(r.x), "=f"(r.y) : "l"(v));
    return r;
}

__device__ __forceinline__ float fast_sigmoid(float v) {
    return __fdividef(1.0f, 1.0f + __expf(-v));
}
__device__ __forceinline__ float fast_tanh(float v) {
    v = fminf(15.0f, fmaxf(-15.0f, v));
    float e = __expf(2.0f * v);
    return __fdividef(e - 1.0f, e + 1.0f);
}

#define TPB_LSTM 128
#define NODES_PER_BLOCK 64   // 4 warps x 16 nodes

__global__ void __launch_bounds__(TPB_LSTM)
lstm_kernel(const float* __restrict__ xg2,     // raw input x [N_TOTAL,2]
            const float* __restrict__ agg2,    // scattered aggregate [N_TOTAL,2]
            const float* __restrict__ dinv,    // [N_TOTAL]
            const float* __restrict__ gcnW, const float* __restrict__ gcnb,
            const float* __restrict__ w_ih, const float* __restrict__ w_hh,
            const float* __restrict__ b_ih, const float* __restrict__ b_hh,
            const float* __restrict__ fcW, const float* __restrict__ fcb,
            float* __restrict__ out) {
    __shared__ float s_wi[4096];
    __shared__ float s_wh[4096];
    __shared__ float s_bias[128];
    __shared__ float s_fcw[32];
    __shared__ float s_gw0[32];
    __shared__ float s_gw1[32];
    __shared__ float s_gb[32];

    int tid = threadIdx.x;
    for (int i = tid; i < 4096; i += TPB_LSTM) {
        s_wi[i] = w_ih[i];
        s_wh[i] = w_hh[i];
    }
    if (tid < 128) s_bias[tid] = b_ih[tid] + b_hh[tid];
    if (tid < 32) {
        s_fcw[tid] = fcW[tid];
        s_gw0[tid] = gcnW[tid];        // gcn_W[0, u]
        s_gw1[tid] = gcnW[32 + tid];   // gcn_W[1, u]
        s_gb[tid] = gcnb[tid];
    }
    __syncthreads();

    int warp = tid >> 5;
    int lane = tid & 31;
    int sub = lane & 15;          // node within warp
    int uhalf = lane >> 4;        // 0: u in [0,16), 1: u in [16,32)
    int ubase = uhalf * 16;

    int node0 = blockIdx.x * NODES_PER_BLOCK + warp * 16 + sub;
    bool valid = node0 < NUM_NODES;
    int node = valid ? node0 : NUM_NODES - 1;

    const float2* xp = (const float2*)(xg2 + (size_t)node * SEQ_LEN * 2);
    const float2* ap = (const float2*)(agg2 + (size_t)node * SEQ_LEN * 2);
    const float* dp = dinv + (size_t)node * SEQ_LEN;

    const float4* wi4 = (const float4*)s_wi;
    const float4* wh4 = (const float4*)s_wh;

    ull x2[16], h2[16];
    float c_own[16];
#pragma unroll
    for (int j = 0; j < 16; j++) { h2[j] = 0ull; c_own[j] = 0.0f; }

    // software-pipelined input loads
    float2 nx = xp[0];
    float2 na = ap[0];
    float nd = dp[0];

#pragma unroll 1
    for (int t = 0; t < SEQ_LEN; t++) {
        float2 xv = nx, av = na;
        float di = nd;
        int tn = t + 1 < SEQ_LEN ? t + 1 : t;
        nx = xp[tn]; na = ap[tn]; nd = dp[tn];

        // fused GCN finalize: x_gcn[k] = relu(v0*W0k + v1*W1k + gb[k]), packed pairs
        float d2 = di * di;
        float v0 = fmaf(xv.x, d2, av.x);
        float v1 = fmaf(xv.y, d2, av.y);
#pragma unroll
        for (int j = 0; j < 16; j++) {
            float a = fmaxf(fmaf(v0, s_gw0[2 * j], fmaf(v1, s_gw1[2 * j], s_gb[2 * j])), 0.0f);
            float b = fmaxf(fmaf(v0, s_gw0[2 * j + 1], fmaf(v1, s_gw1[2 * j + 1], s_gb[2 * j + 1])), 0.0f);
            x2[j] = pk(a, b);
        }

        float h_new[16];
#pragma unroll 2
        for (int uu = 0; uu < 16; uu++) {
            int u = ubase + uu;
            ull ai = 0ull, af = 0ull, ag = 0ull, ao = 0ull;
            const float4* pi = wi4 + (u) * 8;
            const float4* pf = wi4 + (u + 32) * 8;
            const float4* pg = wi4 + (u + 64) * 8;
            const float4* po = wi4 + (u + 96) * 8;
            const float4* qi = wh4 + (u) * 8;
            const float4* qf = wh4 + (u + 32) * 8;
            const float4* qg = wh4 + (u + 64) * 8;
            const float4* qo = wh4 + (u + 96) * 8;
#pragma unroll
            for (int j = 0; j < 8; j++) {
                float4 w;
                w = pi[j];
                ai = ffma2(pk(w.x, w.y), x2[2 * j], ai);
                ai = ffma2(pk(w.z, w.w), x2[2 * j + 1], ai);
                w = qi[j];
                ai = ffma2(pk(w.x, w.y), h2[2 * j], ai);
                ai = ffma2(pk(w.z, w.w), h2[2 * j + 1], ai);
                w = pf[j];
                af = ffma2(pk(w.x, w.y), x2[2 * j], af);
                af = ffma2(pk(w.z, w.w), x2[2 * j + 1], af);
                w = qf[j];
                af = ffma2(pk(w.x, w.y), h2[2 * j], af);
                af = ffma2(pk(w.z, w.w), h2[2 * j + 1], af);
                w = pg[j];
                ag = ffma2(pk(w.x, w.y), x2[2 * j], ag);
                ag = ffma2(pk(w.z, w.w), x2[2 * j + 1], ag);
                w = qg[j];
                ag = ffma2(pk(w.x, w.y), h2[2 * j], ag);
                ag = ffma2(pk(w.z, w.w), h2[2 * j + 1], ag);
                w = po[j];
                ao = ffma2(pk(w.x, w.y), x2[2 * j], ao);
                ao = ffma2(pk(w.z, w.w), x2[2 * j + 1], ao);
                w = qo[j];
                ao = ffma2(pk(w.x, w.y), h2[2 * j], ao);
                ao = ffma2(pk(w.z, w.w), h2[2 * j + 1], ao);
            }
            float2 vi = upk(ai), vf = upk(af), vg = upk(ag), vo = upk(ao);
            float gi = fast_sigmoid(vi.x + vi.y + s_bias[u]);
            float gf = fast_sigmoid(vf.x + vf.y + s_bias[32 + u]);
            float gg = fast_tanh(vg.x + vg.y + s_bias[64 + u]);
            float go = fast_sigmoid(vo.x + vo.y + s_bias[96 + u]);
            float c = fmaf(gf, c_own[uu], gi * gg);
            c_own[uu] = c;
            h_new[uu] = go * fast_tanh(c);
        }

        // exchange h halves within the warp (lanes l <-> l^16)
#pragma unroll
        for (int j = 0; j < 8; j++) {
            ull own = pk(h_new[2 * j], h_new[2 * j + 1]);
            ull oth = __shfl_xor_sync(0xffffffffu, own, 16);
            if (uhalf == 0) { h2[j] = own; h2[8 + j] = oth; }
            else            { h2[j] = oth; h2[8 + j] = own; }
        }
    }

    // fused FC: lower-half thread of each pair stores the output
    if (valid && uhalf == 0) {
        float acc = fcb[0];
#pragma unroll
        for (int j = 0; j < 16; j++) {
            float2 hv = upk(h2[j]);
            acc = fmaf(hv.x, s_fcw[2 * j], acc);
            acc = fmaf(hv.y, s_fcw[2 * j + 1], acc);
        }
        out[node0] = acc;
    }
}

// ---------------------------------------------------------------------------

extern "C" void kernel_launch(void* const* d_in, const int* in_sizes, int n_in,
                              void* d_out, int out_size) {
    const float* x = (const float*)d_in[0];
    const int* ei = (const int*)d_in[1];
    const float* gcnW = (const float*)d_in[2];
    const float* gcnb = (const float*)d_in[3];
    const float* w_ih = (const float*)d_in[4];
    const float* w_hh = (const float*)d_in[5];
    const float* b_ih = (const float*)d_in[6];
    const float* b_hh = (const float*)d_in[7];
    const float* fcW = (const float*)d_in[8];
    const float* fcb = (const float*)d_in[9];
    float* out = (float*)d_out;

    void* aggp = nullptr;
    void* degp = nullptr;
    cudaGetSymbolAddress(&aggp, g_agg2);
    cudaGetSymbolAddress(&degp, g_deg);

    cudaMemsetAsync(aggp, 0, sizeof(float) * (size_t)N_TOTAL * 2);
    cudaMemsetAsync(degp, 0, sizeof(float) * (size_t)N_TOTAL);

    deg_kernel<<<(N_EDGES + 255) / 256, 256>>>(ei, (float*)degp);
    dinv_kernel<<<(N_TOTAL + 255) / 256, 256>>>((float*)degp);
    edge_scatter2<<<(N_EDGES + 255) / 256, 256>>>(ei, x, (const float*)degp, (float*)aggp);

    int lstm_blocks = (NUM_NODES + NODES_PER_BLOCK - 1) / NODES_PER_BLOCK;  // 313
    lstm_kernel<<<lstm_blocks, TPB_LSTM>>>(
        x, (const float*)aggp, (const float*)degp, gcnW, gcnb,
        w_ih, w_hh, b_ih, b_hh, fcW, fcb, out);
}

// round 6
// speedup vs baseline: 1.9883x; 1.9883x over previous
#include <cuda_runtime.h>
#include <cuda_bf16.h>
#include <cstdint>

#define NUM_NODES 20000
#define SEQ_LEN 128
#define HIDDEN 32
#define N_TOTAL (NUM_NODES * SEQ_LEN)        // 2,560,000
#define N_EDGES 2000000

// Scratch: pre-transform aggregate (2 floats per position) + degree. 20MB + 10MB.
__device__ float g_agg2[(size_t)N_TOTAL * 2];
__device__ float g_deg[N_TOTAL];

// ---------------------------------------------------------------------------
// GCN kernels (edge_index arrives as int32)
// ---------------------------------------------------------------------------

__global__ void deg_kernel(const int* __restrict__ ei, float* __restrict__ deg) {
    int e = blockIdx.x * blockDim.x + threadIdx.x;
    if (e < N_EDGES) {
        int dst = ei[N_EDGES + e];
        atomicAdd(deg + dst, 1.0f);
    }
}

__global__ void dinv_kernel(float* __restrict__ deg) {
    int i = blockIdx.x * blockDim.x + threadIdx.x;
    if (i < N_TOTAL) {
        deg[i] = rsqrtf(deg[i] + 1.0f);
    }
}

// thread per edge: agg2[dst] += x[src] * norm   (GCN linearity: W applied later)
__global__ void edge_scatter2(const int* __restrict__ ei,
                              const float* __restrict__ x,
                              const float* __restrict__ dinv,
                              float* __restrict__ agg2) {
    int e = blockIdx.x * blockDim.x + threadIdx.x;
    if (e >= N_EDGES) return;
    int src = ei[e];
    int dst = ei[N_EDGES + e];
    float norm = dinv[src] * dinv[dst];
    float2 xv = *(const float2*)(x + 2 * (size_t)src);
    float* p = agg2 + 2 * (size_t)dst;
    atomicAdd(p, xv.x * norm);
    atomicAdd(p + 1, xv.y * norm);
}

// ---------------------------------------------------------------------------
// LSTM: 2 threads per node (u-halves). Packed f32x2 FMA with weights loaded
// as ulonglong2 (LDS.128 -> two packed operands, no repacking). h exchange
// and c state in padded SMEM (pitch 34 -> 8B-aligned rows, conflict-free
// 64-bit reads).
// ---------------------------------------------------------------------------

typedef unsigned long long ull;

__device__ __forceinline__ ull ffma2(ull a, ull b, ull c) {
    ull d;
    asm("fma.rn.f32x2 %0, %1, %2, %3;" : "=l"(d) : "l"(a), "l"(b), "l"(c));
    return d;
}
__device__ __forceinline__ ull pk(float lo, float hi) {
    ull r;
    asm("mov.b64 %0, {%1, %2};" : "=l"(r) : "f"(lo), "f"(hi));
    return r;
}
__device__ __forceinline__ float2 upk(ull v) {
    float2 r;
    asm("mov.b64 {%0, %1}, %2;" : "=f"(r.x), "=f"(r.y) : "l"(v));
    return r;
}

__device__ __forceinline__ float fast_sigmoid(float v) {
    return __fdividef(1.0f, 1.0f + __expf(-v));
}
__device__ __forceinline__ float fast_tanh(float v) {
    v = fminf(15.0f, fmaxf(-15.0f, v));
    float e = __expf(2.0f * v);
    return __fdividef(e - 1.0f, e + 1.0f);
}

#define TPB_LSTM 128
#define NODES_PER_BLOCK 64   // 4 warps x 16 nodes
#define ST_PITCH 34          // floats per node row (even -> 8B-aligned rows)

__global__ void __launch_bounds__(TPB_LSTM, 2)
lstm_kernel(const float* __restrict__ xg2,     // raw input x [N_TOTAL,2]
            const float* __restrict__ agg2,    // scattered aggregate [N_TOTAL,2]
            const float* __restrict__ dinv,    // [N_TOTAL]
            const float* __restrict__ gcnW, const float* __restrict__ gcnb,
            const float* __restrict__ w_ih, const float* __restrict__ w_hh,
            const float* __restrict__ b_ih, const float* __restrict__ b_hh,
            const float* __restrict__ fcW, const float* __restrict__ fcb,
            float* __restrict__ out) {
    __shared__ __align__(16) float s_wi[4096];
    __shared__ __align__(16) float s_wh[4096];
    __shared__ float s_bias[128];
    __shared__ float s_fcw[32];
    __shared__ float s_gw0[32];
    __shared__ float s_gw1[32];
    __shared__ float s_gb[32];
    __shared__ __align__(16) float s_hx[NODES_PER_BLOCK * ST_PITCH];  // h exchange
    __shared__ float s_c[NODES_PER_BLOCK * ST_PITCH];                 // c state

    int tid = threadIdx.x;
    for (int i = tid; i < 4096; i += TPB_LSTM) {
        s_wi[i] = w_ih[i];
        s_wh[i] = w_hh[i];
    }
    if (tid < 128) s_bias[tid] = b_ih[tid] + b_hh[tid];
    if (tid < 32) {
        s_fcw[tid] = fcW[tid];
        s_gw0[tid] = gcnW[tid];        // gcn_W[0, u]
        s_gw1[tid] = gcnW[32 + tid];   // gcn_W[1, u]
        s_gb[tid] = gcnb[tid];
    }
    for (int i = tid; i < NODES_PER_BLOCK * ST_PITCH; i += TPB_LSTM) {
        s_hx[i] = 0.0f;
        s_c[i] = 0.0f;
    }
    __syncthreads();

    int warp = tid >> 5;
    int lane = tid & 31;
    int sub = lane & 15;          // node within warp
    int uhalf = lane >> 4;        // 0: u in [0,16), 1: u in [16,32)
    int ubase = uhalf * 16;
    int nib = warp * 16 + sub;    // node index in block

    int node0 = blockIdx.x * NODES_PER_BLOCK + nib;
    bool valid = node0 < NUM_NODES;
    int node = valid ? node0 : NUM_NODES - 1;

    const float2* xp = (const float2*)(xg2 + (size_t)node * SEQ_LEN * 2);
    const float2* ap = (const float2*)(agg2 + (size_t)node * SEQ_LEN * 2);
    const float* dp = dinv + (size_t)node * SEQ_LEN;

    float* my_c = s_c + nib * ST_PITCH + ubase;   // 16 private floats
    float* my_hx = s_hx + nib * ST_PITCH;         // 32 shared-with-partner floats

    ull x2[16], h2[16];
#pragma unroll
    for (int j = 0; j < 16; j++) h2[j] = 0ull;

    // software-pipelined input loads
    float2 nx = xp[0];
    float2 na = ap[0];
    float nd = dp[0];

#pragma unroll 1
    for (int t = 0; t < SEQ_LEN; t++) {
        float2 xv = nx, av = na;
        float di = nd;
        int tn = t + 1 < SEQ_LEN ? t + 1 : t;
        nx = xp[tn]; na = ap[tn]; nd = dp[tn];

        // fused GCN finalize: x_gcn[k] = relu(v0*W0k + v1*W1k + gb[k]), packed
        float d2 = di * di;
        float v0 = fmaf(xv.x, d2, av.x);
        float v1 = fmaf(xv.y, d2, av.y);
#pragma unroll
        for (int j = 0; j < 16; j++) {
            float a = fmaxf(fmaf(v0, s_gw0[2 * j], fmaf(v1, s_gw1[2 * j], s_gb[2 * j])), 0.0f);
            float b = fmaxf(fmaf(v0, s_gw0[2 * j + 1], fmaf(v1, s_gw1[2 * j + 1], s_gb[2 * j + 1])), 0.0f);
            x2[j] = pk(a, b);
        }

#pragma unroll 4
        for (int uu = 0; uu < 16; uu++) {
            int u = ubase + uu;
            const ulonglong2* pxi = (const ulonglong2*)(s_wi + u * 32);
            const ulonglong2* pxf = (const ulonglong2*)(s_wi + (u + 32) * 32);
            const ulonglong2* pxg = (const ulonglong2*)(s_wi + (u + 64) * 32);
            const ulonglong2* pxo = (const ulonglong2*)(s_wi + (u + 96) * 32);
            const ulonglong2* phi = (const ulonglong2*)(s_wh + u * 32);
            const ulonglong2* phf = (const ulonglong2*)(s_wh + (u + 32) * 32);
            const ulonglong2* phg = (const ulonglong2*)(s_wh + (u + 64) * 32);
            const ulonglong2* pho = (const ulonglong2*)(s_wh + (u + 96) * 32);
            ull axi = 0, axf = 0, axg = 0, axo = 0;
            ull ahi = 0, ahf = 0, ahg = 0, aho = 0;
#pragma unroll
            for (int j = 0; j < 8; j++) {
                ulonglong2 w;
                w = pxi[j]; axi = ffma2(w.x, x2[2 * j], axi); axi = ffma2(w.y, x2[2 * j + 1], axi);
                w = phi[j]; ahi = ffma2(w.x, h2[2 * j], ahi); ahi = ffma2(w.y, h2[2 * j + 1], ahi);
                w = pxf[j]; axf = ffma2(w.x, x2[2 * j], axf); axf = ffma2(w.y, x2[2 * j + 1], axf);
                w = phf[j]; ahf = ffma2(w.x, h2[2 * j], ahf); ahf = ffma2(w.y, h2[2 * j + 1], ahf);
                w = pxg[j]; axg = ffma2(w.x, x2[2 * j], axg); axg = ffma2(w.y, x2[2 * j + 1], axg);
                w = phg[j]; ahg = ffma2(w.x, h2[2 * j], ahg); ahg = ffma2(w.y, h2[2 * j + 1], ahg);
                w = pxo[j]; axo = ffma2(w.x, x2[2 * j], axo); axo = ffma2(w.y, x2[2 * j + 1], axo);
                w = pho[j]; aho = ffma2(w.x, h2[2 * j], aho); aho = ffma2(w.y, h2[2 * j + 1], aho);
            }
            float2 vxi = upk(axi), vhi = upk(ahi);
            float2 vxf = upk(axf), vhf = upk(ahf);
            float2 vxg = upk(axg), vhg = upk(ahg);
            float2 vxo = upk(axo), vho = upk(aho);
            float gi = fast_sigmoid(vxi.x + vxi.y + vhi.x + vhi.y + s_bias[u]);
            float gf = fast_sigmoid(vxf.x + vxf.y + vhf.x + vhf.y + s_bias[32 + u]);
            float gg = fast_tanh(vxg.x + vxg.y + vhg.x + vhg.y + s_bias[64 + u]);
            float go = fast_sigmoid(vxo.x + vxo.y + vho.x + vho.y + s_bias[96 + u]);
            float c = fmaf(gf, my_c[uu], gi * gg);
            my_c[uu] = c;
            my_hx[ubase + uu] = go * fast_tanh(c);   // publish h for both halves
        }

        __syncwarp();
#pragma unroll
        for (int j = 0; j < 16; j++) h2[j] = *(const ull*)(my_hx + 2 * j);
        __syncwarp();
    }

    // fused FC: lower-half thread of each pair stores the output
    if (valid && uhalf == 0) {
        float acc = fcb[0];
#pragma unroll
        for (int j = 0; j < 16; j++) {
            float2 hv = upk(h2[j]);
            acc = fmaf(hv.x, s_fcw[2 * j], acc);
            acc = fmaf(hv.y, s_fcw[2 * j + 1], acc);
        }
        out[node0] = acc;
    }
}

// ---------------------------------------------------------------------------

extern "C" void kernel_launch(void* const* d_in, const int* in_sizes, int n_in,
                              void* d_out, int out_size) {
    const float* x = (const float*)d_in[0];
    const int* ei = (const int*)d_in[1];
    const float* gcnW = (const float*)d_in[2];
    const float* gcnb = (const float*)d_in[3];
    const float* w_ih = (const float*)d_in[4];
    const float* w_hh = (const float*)d_in[5];
    const float* b_ih = (const float*)d_in[6];
    const float* b_hh = (const float*)d_in[7];
    const float* fcW = (const float*)d_in[8];
    const float* fcb = (const float*)d_in[9];
    float* out = (float*)d_out;

    void* aggp = nullptr;
    void* degp = nullptr;
    cudaGetSymbolAddress(&aggp, g_agg2);
    cudaGetSymbolAddress(&degp, g_deg);

    cudaMemsetAsync(aggp, 0, sizeof(float) * (size_t)N_TOTAL * 2);
    cudaMemsetAsync(degp, 0, sizeof(float) * (size_t)N_TOTAL);

    deg_kernel<<<(N_EDGES + 255) / 256, 256>>>(ei, (float*)degp);
    dinv_kernel<<<(N_TOTAL + 255) / 256, 256>>>((float*)degp);
    edge_scatter2<<<(N_EDGES + 255) / 256, 256>>>(ei, x, (const float*)degp, (float*)aggp);

    int lstm_blocks = (NUM_NODES + NODES_PER_BLOCK - 1) / NODES_PER_BLOCK;  // 313
    lstm_kernel<<<lstm_blocks, TPB_LSTM>>>(
        x, (const float*)aggp, (const float*)degp, gcnW, gcnb,
        w_ih, w_hh, b_ih, b_hh, fcW, fcb, out);
}

// round 7
// speedup vs baseline: 2.0574x; 1.0347x over previous
#include <cuda_runtime.h>
#include <cuda_bf16.h>
#include <cstdint>

#define NUM_NODES 20000
#define SEQ_LEN 128
#define HIDDEN 32
#define N_TOTAL (NUM_NODES * SEQ_LEN)        // 2,560,000
#define N_EDGES 2000000

// Scratch: pre-transform aggregate (2 floats per position) + degree. 20MB + 10MB.
__device__ float g_agg2[(size_t)N_TOTAL * 2];
__device__ float g_deg[N_TOTAL];

// ---------------------------------------------------------------------------
// GCN kernels (edge_index arrives as int32)
// ---------------------------------------------------------------------------

__global__ void deg_kernel(const int* __restrict__ ei, float* __restrict__ deg) {
    int e = blockIdx.x * blockDim.x + threadIdx.x;
    if (e < N_EDGES) {
        int dst = ei[N_EDGES + e];
        atomicAdd(deg + dst, 1.0f);
    }
}

__global__ void dinv_kernel(float* __restrict__ deg) {
    int i = blockIdx.x * blockDim.x + threadIdx.x;
    if (i < N_TOTAL) {
        deg[i] = rsqrtf(deg[i] + 1.0f);
    }
}

// thread per edge: agg2[dst] += x[src] * norm   (GCN linearity: W applied later)
__global__ void edge_scatter2(const int* __restrict__ ei,
                              const float* __restrict__ x,
                              const float* __restrict__ dinv,
                              float* __restrict__ agg2) {
    int e = blockIdx.x * blockDim.x + threadIdx.x;
    if (e >= N_EDGES) return;
    int src = ei[e];
    int dst = ei[N_EDGES + e];
    float norm = dinv[src] * dinv[dst];
    float2 xv = *(const float2*)(x + 2 * (size_t)src);
    float* p = agg2 + 2 * (size_t)dst;
    atomicAdd(p, xv.x * norm);
    atomicAdd(p + 1, xv.y * norm);
}

// ---------------------------------------------------------------------------
// LSTM v3: warp-uniform weights. A warp = 32 nodes (one per lane), computing
// one u-half (16 gate rows); the partner warp computes the other half. Every
// weight LDS.128 is a single-address broadcast serving 32 nodes. h exchanged
// between partner warps via padded SMEM + 2 barriers per step.
// ---------------------------------------------------------------------------

typedef unsigned long long ull;

__device__ __forceinline__ ull ffma2(ull a, ull b, ull c) {
    ull d;
    asm("fma.rn.f32x2 %0, %1, %2, %3;" : "=l"(d) : "l"(a), "l"(b), "l"(c));
    return d;
}
__device__ __forceinline__ ull pk(float lo, float hi) {
    ull r;
    asm("mov.b64 %0, {%1, %2};" : "=l"(r) : "f"(lo), "f"(hi));
    return r;
}
__device__ __forceinline__ float2 upk(ull v) {
    float2 r;
    asm("mov.b64 {%0, %1}, %2;" : "=f"(r.x), "=f"(r.y) : "l"(v));
    return r;
}

__device__ __forceinline__ float fast_sigmoid(float v) {
    return __fdividef(1.0f, 1.0f + __expf(-v));
}
__device__ __forceinline__ float fast_tanh(float v) {
    v = fminf(15.0f, fmaxf(-15.0f, v));
    float e = __expf(2.0f * v);
    return __fdividef(e - 1.0f, e + 1.0f);
}

#define TPB_LSTM 128
#define NODES_PER_BLOCK 64   // warp pair (0,1) -> nodes [0,32), pair (2,3) -> [32,64)
#define ST_PITCH 34          // even pitch -> 8B-aligned rows, conflict-free

__global__ void __launch_bounds__(TPB_LSTM)
lstm_kernel(const float* __restrict__ xg2,     // raw input x [N_TOTAL,2]
            const float* __restrict__ agg2,    // scattered aggregate [N_TOTAL,2]
            const float* __restrict__ dinv,    // [N_TOTAL]
            const float* __restrict__ gcnW, const float* __restrict__ gcnb,
            const float* __restrict__ w_ih, const float* __restrict__ w_hh,
            const float* __restrict__ b_ih, const float* __restrict__ b_hh,
            const float* __restrict__ fcW, const float* __restrict__ fcb,
            float* __restrict__ out) {
    __shared__ __align__(16) float s_wi[4096];
    __shared__ __align__(16) float s_wh[4096];
    __shared__ float s_bias[128];
    __shared__ float s_fcw[32];
    __shared__ float s_gw0[32];
    __shared__ float s_gw1[32];
    __shared__ float s_gb[32];
    __shared__ __align__(16) float s_hx[NODES_PER_BLOCK * ST_PITCH];  // h exchange
    __shared__ float s_c[NODES_PER_BLOCK * ST_PITCH];                 // c state

    int tid = threadIdx.x;
    for (int i = tid; i < 4096; i += TPB_LSTM) {
        s_wi[i] = w_ih[i];
        s_wh[i] = w_hh[i];
    }
    if (tid < 128) s_bias[tid] = b_ih[tid] + b_hh[tid];
    if (tid < 32) {
        s_fcw[tid] = fcW[tid];
        s_gw0[tid] = gcnW[tid];        // gcn_W[0, u]
        s_gw1[tid] = gcnW[32 + tid];   // gcn_W[1, u]
        s_gb[tid] = gcnb[tid];
    }
    for (int i = tid; i < NODES_PER_BLOCK * ST_PITCH; i += TPB_LSTM) {
        s_hx[i] = 0.0f;
        s_c[i] = 0.0f;
    }
    __syncthreads();

    int warp = tid >> 5;
    int lane = tid & 31;
    int pair = warp >> 1;         // node-group within block
    int uhalf = warp & 1;         // warp-uniform u-half
    int ubase = uhalf * 16;
    int nib = pair * 32 + lane;   // node index in block

    int node0 = blockIdx.x * NODES_PER_BLOCK + nib;
    bool valid = node0 < NUM_NODES;
    int node = valid ? node0 : NUM_NODES - 1;

    const float2* xp = (const float2*)(xg2 + (size_t)node * SEQ_LEN * 2);
    const float2* ap = (const float2*)(agg2 + (size_t)node * SEQ_LEN * 2);
    const float* dp = dinv + (size_t)node * SEQ_LEN;

    float* my_c = s_c + nib * ST_PITCH + ubase;   // 16 private floats
    float* my_hx = s_hx + nib * ST_PITCH;         // 32 floats shared with partner warp

    ull x2[16], h2[16];
#pragma unroll
    for (int j = 0; j < 16; j++) h2[j] = 0ull;

    // software-pipelined input loads
    float2 nx = xp[0];
    float2 na = ap[0];
    float nd = dp[0];

#pragma unroll 1
    for (int t = 0; t < SEQ_LEN; t++) {
        float2 xv = nx, av = na;
        float di = nd;
        int tn = t + 1 < SEQ_LEN ? t + 1 : t;
        nx = xp[tn]; na = ap[tn]; nd = dp[tn];

        // fused GCN finalize: x_gcn[k] = relu(v0*W0k + v1*W1k + gb[k]), packed
        float d2 = di * di;
        float v0 = fmaf(xv.x, d2, av.x);
        float v1 = fmaf(xv.y, d2, av.y);
#pragma unroll
        for (int j = 0; j < 16; j++) {
            float a = fmaxf(fmaf(v0, s_gw0[2 * j], fmaf(v1, s_gw1[2 * j], s_gb[2 * j])), 0.0f);
            float b = fmaxf(fmaf(v0, s_gw0[2 * j + 1], fmaf(v1, s_gw1[2 * j + 1], s_gb[2 * j + 1])), 0.0f);
            x2[j] = pk(a, b);
        }

#pragma unroll 4
        for (int uu = 0; uu < 16; uu++) {
            int u = ubase + uu;                    // warp-uniform
            const ulonglong2* pxi = (const ulonglong2*)(s_wi + u * 32);
            const ulonglong2* pxf = (const ulonglong2*)(s_wi + (u + 32) * 32);
            const ulonglong2* pxg = (const ulonglong2*)(s_wi + (u + 64) * 32);
            const ulonglong2* pxo = (const ulonglong2*)(s_wi + (u + 96) * 32);
            const ulonglong2* phi = (const ulonglong2*)(s_wh + u * 32);
            const ulonglong2* phf = (const ulonglong2*)(s_wh + (u + 32) * 32);
            const ulonglong2* phg = (const ulonglong2*)(s_wh + (u + 64) * 32);
            const ulonglong2* pho = (const ulonglong2*)(s_wh + (u + 96) * 32);
            ull ai = 0, af = 0, ag = 0, ao = 0;    // merged x+h accumulators
#pragma unroll
            for (int j = 0; j < 8; j++) {
                ulonglong2 w;
                w = pxi[j]; ai = ffma2(w.x, x2[2 * j], ai); ai = ffma2(w.y, x2[2 * j + 1], ai);
                w = pxf[j]; af = ffma2(w.x, x2[2 * j], af); af = ffma2(w.y, x2[2 * j + 1], af);
                w = pxg[j]; ag = ffma2(w.x, x2[2 * j], ag); ag = ffma2(w.y, x2[2 * j + 1], ag);
                w = pxo[j]; ao = ffma2(w.x, x2[2 * j], ao); ao = ffma2(w.y, x2[2 * j + 1], ao);
                w = phi[j]; ai = ffma2(w.x, h2[2 * j], ai); ai = ffma2(w.y, h2[2 * j + 1], ai);
                w = phf[j]; af = ffma2(w.x, h2[2 * j], af); af = ffma2(w.y, h2[2 * j + 1], af);
                w = phg[j]; ag = ffma2(w.x, h2[2 * j], ag); ag = ffma2(w.y, h2[2 * j + 1], ag);
                w = pho[j]; ao = ffma2(w.x, h2[2 * j], ao); ao = ffma2(w.y, h2[2 * j + 1], ao);
            }
            float2 vi = upk(ai), vf = upk(af), vg = upk(ag), vo = upk(ao);
            float gi = fast_sigmoid(vi.x + vi.y + s_bias[u]);
            float gf = fast_sigmoid(vf.x + vf.y + s_bias[32 + u]);
            float gg = fast_tanh(vg.x + vg.y + s_bias[64 + u]);
            float go = fast_sigmoid(vo.x + vo.y + s_bias[96 + u]);
            float c = fmaf(gf, my_c[uu], gi * gg);
            my_c[uu] = c;
            my_hx[ubase + uu] = go * fast_tanh(c);   // publish h half
        }

        __syncthreads();   // partner warp's h published
#pragma unroll
        for (int j = 0; j < 16; j++) h2[j] = *(const ull*)(my_hx + 2 * j);
        __syncthreads();   // everyone has read before next-step writes
    }

    // fused FC: uhalf-0 warp of each pair stores the output
    if (valid && uhalf == 0) {
        float acc = fcb[0];
#pragma unroll
        for (int j = 0; j < 16; j++) {
            float2 hv = upk(h2[j]);
            acc = fmaf(hv.x, s_fcw[2 * j], acc);
            acc = fmaf(hv.y, s_fcw[2 * j + 1], acc);
        }
        out[node0] = acc;
    }
}

// ---------------------------------------------------------------------------

extern "C" void kernel_launch(void* const* d_in, const int* in_sizes, int n_in,
                              void* d_out, int out_size) {
    const float* x = (const float*)d_in[0];
    const int* ei = (const int*)d_in[1];
    const float* gcnW = (const float*)d_in[2];
    const float* gcnb = (const float*)d_in[3];
    const float* w_ih = (const float*)d_in[4];
    const float* w_hh = (const float*)d_in[5];
    const float* b_ih = (const float*)d_in[6];
    const float* b_hh = (const float*)d_in[7];
    const float* fcW = (const float*)d_in[8];
    const float* fcb = (const float*)d_in[9];
    float* out = (float*)d_out;

    void* aggp = nullptr;
    void* degp = nullptr;
    cudaGetSymbolAddress(&aggp, g_agg2);
    cudaGetSymbolAddress(&degp, g_deg);

    cudaMemsetAsync(aggp, 0, sizeof(float) * (size_t)N_TOTAL * 2);
    cudaMemsetAsync(degp, 0, sizeof(float) * (size_t)N_TOTAL);

    deg_kernel<<<(N_EDGES + 255) / 256, 256>>>(ei, (float*)degp);
    dinv_kernel<<<(N_TOTAL + 255) / 256, 256>>>((float*)degp);
    edge_scatter2<<<(N_EDGES + 255) / 256, 256>>>(ei, x, (const float*)degp, (float*)aggp);

    int lstm_blocks = (NUM_NODES + NODES_PER_BLOCK - 1) / NODES_PER_BLOCK;  // 313
    lstm_kernel<<<lstm_blocks, TPB_LSTM>>>(
        x, (const float*)aggp, (const float*)degp, gcnW, gcnb,
        w_ih, w_hh, b_ih, b_hh, fcW, fcb, out);
}